// round 1
// baseline (speedup 1.0000x reference)
#include <cuda_runtime.h>
#include <math.h>

typedef unsigned long long u64;

#define BATCH 128
#define HDIM  1024
#define G4    4096

// ---------------- static device scratch (no allocations allowed) ----------------
__device__ float g_P  [(size_t)256 * BATCH * G4];    // 512 MiB: pre-activations for current phase
__device__ float g_hsA[(size_t)256 * BATCH * HDIM];  // 128 MiB: enc L0 hs, reused as dec L0 hs
__device__ float g_hsB[(size_t)128 * BATCH * HDIM];  //  64 MiB: dec L1 hs (head input)
__device__ float g_c0 [BATCH * HDIM];                // layer-0 cell state (enc then dec, in place)
__device__ float g_c1 [BATCH * HDIM];                // layer-1 cell state
__device__ float g_pp [2][BATCH * HDIM];             // h ping-pong for layer-1 recurrences
__device__ float g_zero[BATCH * HDIM];               // all-zero h (never written after init)

// ---------------- f32x2 helpers ----------------
__device__ __forceinline__ u64 pk2(float lo, float hi) {
    u64 r; asm("mov.b64 %0,{%1,%2};" : "=l"(r) : "f"(lo), "f"(hi)); return r;
}
__device__ __forceinline__ void up2(u64 v, float &lo, float &hi) {
    asm("mov.b64 {%0,%1},%2;" : "=f"(lo), "=f"(hi) : "l"(v));
}
__device__ __forceinline__ void ffma2(u64 &d, u64 a, u64 b) {
    asm("fma.rn.f32x2 %0,%1,%2,%0;" : "+l"(d) : "l"(a), "l"(b));
}
__device__ __forceinline__ float sigf(float x) { return 1.0f / (1.0f + expf(-x)); }

// ---------------- init: zero states + the zeros output section ----------------
__global__ void init_kernel(float *out) {
    int i = blockIdx.x * blockDim.x + threadIdx.x;
    if (i < BATCH * HDIM) {
        g_c0[i] = 0.f; g_c1[i] = 0.f;
        g_pp[0][i] = 0.f; g_pp[1][i] = 0.f;
        g_zero[i] = 0.f;
    }
    if (i < 16384) out[i] = 0.f;   // output_collection = zeros
}

// ---------------- P for encoder L0: P[t*B+b][n] = x[b][t][:8] . Wih0[n][:8] + bih+bhh ----------------
__global__ __launch_bounds__(256) void p_enc0_kernel(
    const float* __restrict__ x, const float* __restrict__ W,
    const float* __restrict__ b1, const float* __restrict__ b2)
{
    int idx = blockIdx.x * 256 + threadIdx.x;       // 256*128*1024 float4 units
    int n4 = idx & 1023;
    int b  = (idx >> 10) & 127;
    int t  = idx >> 17;
    const float* xp = x + ((size_t)b * 256 + t) * 8;
    float4 xa = *(const float4*)xp;
    float4 xb = *(const float4*)(xp + 4);
    float res[4];
#pragma unroll
    for (int u = 0; u < 4; u++) {
        int n = n4 * 4 + u;
        const float* wr = W + (size_t)n * 8;
        float4 wa = *(const float4*)wr;
        float4 wb = *(const float4*)(wr + 4);
        res[u] = xa.x*wa.x + xa.y*wa.y + xa.z*wa.z + xa.w*wa.w
               + xb.x*wb.x + xb.y*wb.y + xb.z*wb.z + xb.w*wb.w
               + b1[n] + b2[n];
    }
    *(float4*)(g_P + ((size_t)t * BATCH + b) * G4 + n4 * 4) = make_float4(res[0], res[1], res[2], res[3]);
}

// ---------------- P for decoder L0: P[t*B+b][n] = y[b][t] * Wih0[n] + bih+bhh ----------------
__global__ __launch_bounds__(256) void p_dec0_kernel(
    const float* __restrict__ y, const float* __restrict__ W,
    const float* __restrict__ b1, const float* __restrict__ b2)
{
    int idx = blockIdx.x * 256 + threadIdx.x;       // 128*128*1024 float4 units
    int n4 = idx & 1023;
    int b  = (idx >> 10) & 127;
    int t  = idx >> 17;
    float yv = y[(size_t)b * 129 + t];
    float4 w  = *(const float4*)(W  + n4 * 4);
    float4 v1 = *(const float4*)(b1 + n4 * 4);
    float4 v2 = *(const float4*)(b2 + n4 * 4);
    float4 r;
    r.x = yv * w.x + v1.x + v2.x;
    r.y = yv * w.y + v1.y + v2.y;
    r.z = yv * w.z + v1.z + v2.z;
    r.w = yv * w.w + v1.w + v2.w;
    *(float4*)(g_P + ((size_t)t * BATCH + b) * G4 + n4 * 4) = r;
}

// ---------------- big input GEMM: g_P[m][n] = bias[n] + sum_k g_hsA[m][k] * W[n][k] ----------------
// grid: (32 n-tiles of 128, M/128 m-tiles), 256 threads, 128x128 tile, 8m x 8n per thread (f32x2 on m-pairs)
__global__ __launch_bounds__(256) void gemm_bias_kernel(
    const float* __restrict__ W, const float* __restrict__ b1, const float* __restrict__ b2)
{
    constexpr int KC = 32;
    __shared__ __align__(16) float sA[KC][130];
    __shared__ __align__(16) float sW[KC][132];
    int tid = threadIdx.x;
    int tn = tid & 15, tm = tid >> 4;
    size_t m0 = (size_t)blockIdx.y * 128;
    int n0 = blockIdx.x * 128;

    u64 acc[8][4];
#pragma unroll
    for (int n = 0; n < 8; n++)
#pragma unroll
        for (int p = 0; p < 4; p++) acc[n][p] = 0ull;

    const float* A = g_hsA;
    for (int k0 = 0; k0 < HDIM; k0 += KC) {
#pragma unroll
        for (int bb = 0; bb < 128; bb += 32) {
            int r = bb + (tid >> 3);
            int kk = (tid & 7) * 4;
            float4 v = *(const float4*)(A + (m0 + r) * HDIM + k0 + kk);
            sA[kk+0][r] = v.x; sA[kk+1][r] = v.y; sA[kk+2][r] = v.z; sA[kk+3][r] = v.w;
        }
#pragma unroll
        for (int l = tid; l < 1024; l += 256) {
            int r = l >> 3;
            int kk = (l & 7) * 4;
            float4 v = *(const float4*)(W + (size_t)(n0 + r) * HDIM + k0 + kk);
            sW[kk+0][r] = v.x; sW[kk+1][r] = v.y; sW[kk+2][r] = v.z; sW[kk+3][r] = v.w;
        }
        __syncthreads();
#pragma unroll
        for (int k = 0; k < KC; k++) {
            float2 h0 = *(const float2*)&sA[k][tm*8 + 0];
            float2 h1 = *(const float2*)&sA[k][tm*8 + 2];
            float2 h2 = *(const float2*)&sA[k][tm*8 + 4];
            float2 h3 = *(const float2*)&sA[k][tm*8 + 6];
            u64 a0 = pk2(h0.x, h0.y), a1 = pk2(h1.x, h1.y);
            u64 a2 = pk2(h2.x, h2.y), a3 = pk2(h3.x, h3.y);
            float4 wa = *(const float4*)&sW[k][tn*8];
            float4 wb = *(const float4*)&sW[k][tn*8 + 4];
            u64 w[8] = { pk2(wa.x,wa.x), pk2(wa.y,wa.y), pk2(wa.z,wa.z), pk2(wa.w,wa.w),
                         pk2(wb.x,wb.x), pk2(wb.y,wb.y), pk2(wb.z,wb.z), pk2(wb.w,wb.w) };
#pragma unroll
            for (int n = 0; n < 8; n++) {
                ffma2(acc[n][0], a0, w[n]);
                ffma2(acc[n][1], a1, w[n]);
                ffma2(acc[n][2], a2, w[n]);
                ffma2(acc[n][3], a3, w[n]);
            }
        }
        __syncthreads();
    }

    int nbase = n0 + tn * 8;
    float bias[8];
#pragma unroll
    for (int n = 0; n < 8; n++) bias[n] = b1[nbase + n] + b2[nbase + n];
#pragma unroll
    for (int p = 0; p < 4; p++) {
#pragma unroll
        for (int s = 0; s < 2; s++) {
            float vals[8];
#pragma unroll
            for (int n = 0; n < 8; n++) {
                float lo, hi; up2(acc[n][p], lo, hi);
                vals[n] = (s ? hi : lo) + bias[n];
            }
            size_t m = m0 + tm * 8 + 2 * p + s;
            *(float4*)(g_P + m * G4 + nbase)     = make_float4(vals[0], vals[1], vals[2], vals[3]);
            *(float4*)(g_P + m * G4 + nbase + 4) = make_float4(vals[4], vals[5], vals[6], vals[7]);
        }
    }
}

// ---------------- fused LSTM step: G = P[t] + h_in @ Whh^T ; gates; update h,c ----------------
// grid: 128 blocks (8 j-cols each, all 4 gates), 128 threads.
// thread: jj = tid&7 (one j), bg = tid>>3 (8 batch rows = 4 f32x2 pairs), 4 gates -> 16 acc2.
// phase: 0=enc L0, 1=enc L1, 2=dec L0, 3=dec L1
__global__ __launch_bounds__(128) void lstm_step_kernel(
    const float* __restrict__ Whh, int t, int phase)
{
    constexpr int KC = 32;
    constexpr size_t BH = (size_t)BATCH * HDIM;
    __shared__ __align__(16) float sh[KC][130];   // h^T tile  [k][b]
    __shared__ __align__(16) float sw[KC][36];    // W tile    [k][jj*4+gate]

    const float* P = g_P + (size_t)t * BATCH * G4;
    const float* h_in; float* h_out; float* c;
    if (phase == 0) {
        h_in = (t == 0) ? g_zero : g_hsA + (size_t)(t - 1) * BH;
        h_out = g_hsA + (size_t)t * BH;  c = g_c0;
    } else if (phase == 1) {
        h_in = g_pp[t & 1]; h_out = g_pp[(t + 1) & 1]; c = g_c1;
    } else if (phase == 2) {
        h_in = (t == 0) ? g_hsA + (size_t)255 * BH : g_hsA + (size_t)(t - 1) * BH;
        h_out = g_hsA + (size_t)t * BH;  c = g_c0;
    } else {
        h_in = (t == 0) ? g_pp[0] : g_hsB + (size_t)(t - 1) * BH;
        h_out = g_hsB + (size_t)t * BH;  c = g_c1;
    }

    int tid = threadIdx.x;
    int jj = tid & 7;
    int bg = tid >> 3;            // 0..15  (b base = bg*8)
    int j0 = blockIdx.x * 8;
    int j  = j0 + jj;

    u64 acc[4][4];                 // [gate][b-pair]
#pragma unroll
    for (int gi = 0; gi < 4; gi++)
#pragma unroll
        for (int p = 0; p < 4; p++) acc[gi][p] = 0ull;

    for (int k0 = 0; k0 < HDIM; k0 += KC) {
        // stage h^T tile (coalesced along k)
#pragma unroll
        for (int bb = 0; bb < 128; bb += 16) {
            int b = bb + (tid >> 3);
            int kk = (tid & 7) * 4;
            float4 v = *(const float4*)(h_in + (size_t)b * HDIM + k0 + kk);
            sh[kk+0][b] = v.x; sh[kk+1][b] = v.y; sh[kk+2][b] = v.z; sh[kk+3][b] = v.w;
        }
        // stage W tile: rows n = gate*1024 + j0 + wjj
#pragma unroll
        for (int l = tid; l < 256; l += 128) {
            int cc = l >> 3;
            int kk = (l & 7) * 4;
            int wjj = cc >> 2, gi = cc & 3;
            float4 v = *(const float4*)(Whh + (size_t)(gi * HDIM + j0 + wjj) * HDIM + k0 + kk);
            sw[kk+0][wjj*4+gi] = v.x; sw[kk+1][wjj*4+gi] = v.y;
            sw[kk+2][wjj*4+gi] = v.z; sw[kk+3][wjj*4+gi] = v.w;
        }
        __syncthreads();
#pragma unroll
        for (int k = 0; k < KC; k++) {
            float2 h0 = *(const float2*)&sh[k][bg*8 + 0];
            float2 h1 = *(const float2*)&sh[k][bg*8 + 2];
            float2 h2 = *(const float2*)&sh[k][bg*8 + 4];
            float2 h3 = *(const float2*)&sh[k][bg*8 + 6];
            u64 a0 = pk2(h0.x, h0.y), a1 = pk2(h1.x, h1.y);
            u64 a2 = pk2(h2.x, h2.y), a3 = pk2(h3.x, h3.y);
            float4 w = *(const float4*)&sw[k][jj*4];
            u64 w0 = pk2(w.x, w.x), w1 = pk2(w.y, w.y), w2 = pk2(w.z, w.z), w3 = pk2(w.w, w.w);
            ffma2(acc[0][0], a0, w0); ffma2(acc[0][1], a1, w0); ffma2(acc[0][2], a2, w0); ffma2(acc[0][3], a3, w0);
            ffma2(acc[1][0], a0, w1); ffma2(acc[1][1], a1, w1); ffma2(acc[1][2], a2, w1); ffma2(acc[1][3], a3, w1);
            ffma2(acc[2][0], a0, w2); ffma2(acc[2][1], a1, w2); ffma2(acc[2][2], a2, w2); ffma2(acc[2][3], a3, w2);
            ffma2(acc[3][0], a0, w3); ffma2(acc[3][1], a1, w3); ffma2(acc[3][2], a2, w3); ffma2(acc[3][3], a3, w3);
        }
        __syncthreads();
    }

    // epilogue: gates + state update
#pragma unroll
    for (int p = 0; p < 4; p++) {
        float vi[2], vf[2], vg[2], vo[2];
        up2(acc[0][p], vi[0], vi[1]);
        up2(acc[1][p], vf[0], vf[1]);
        up2(acc[2][p], vg[0], vg[1]);
        up2(acc[3][p], vo[0], vo[1]);
        int b0 = bg * 8 + 2 * p;
#pragma unroll
        for (int s = 0; s < 2; s++) {
            int b = b0 + s;
            const float* Pb = P + (size_t)b * G4;
            float gi = sigf(vi[s] + Pb[j]);
            float gf = sigf(vf[s] + Pb[HDIM + j]);
            float gg = tanhf(vg[s] + Pb[2 * HDIM + j]);
            float go = sigf(vo[s] + Pb[3 * HDIM + j]);
            size_t ci = (size_t)b * HDIM + j;
            float cn = gf * c[ci] + gi * gg;
            c[ci] = cn;
            h_out[ci] = go * tanhf(cn);
        }
    }
}

// ---------------- head: mu / softplus(sigma) from g_hsB ----------------
__global__ __launch_bounds__(256) void head_kernel(
    const float* __restrict__ Wmu, const float* __restrict__ bmu,
    const float* __restrict__ Wsig, const float* __restrict__ bsig,
    float* __restrict__ out)
{
    int gw = (blockIdx.x * 256 + threadIdx.x) >> 5;   // 0..16383, = t*128 + b
    int lane = threadIdx.x & 31;
    if (gw >= 16384) return;
    const float* h = g_hsB + (size_t)gw * HDIM;
    float smu = 0.f, ssg = 0.f;
#pragma unroll 8
    for (int i = lane; i < HDIM; i += 32) {
        float hv = h[i];
        smu += hv * Wmu[i];
        ssg += hv * Wsig[i];
    }
#pragma unroll
    for (int off = 16; off > 0; off >>= 1) {
        smu += __shfl_xor_sync(0xFFFFFFFFu, smu, off);
        ssg += __shfl_xor_sync(0xFFFFFFFFu, ssg, off);
    }
    if (lane == 0) {
        int b = gw & 127;
        int t = gw >> 7;
        float mu = smu + bmu[0];
        float z  = ssg + bsig[0];
        float sp = (z > 0.f) ? (z + log1pf(expf(-z))) : log1pf(expf(z));
        out[16384 + b * 128 + t] = mu;
        out[32768 + b * 128 + t] = sp;
    }
}

// ---------------- launch ----------------
extern "C" void kernel_launch(void* const* d_in, const int* in_sizes, int n_in,
                              void* d_out, int out_size)
{
    (void)in_sizes; (void)n_in; (void)out_size;
    const float* x     = (const float*)d_in[0];
    const float* y     = (const float*)d_in[1];
    const float* eWih0 = (const float*)d_in[2];
    const float* eWhh0 = (const float*)d_in[3];
    const float* ebih0 = (const float*)d_in[4];
    const float* ebhh0 = (const float*)d_in[5];
    const float* eWih1 = (const float*)d_in[6];
    const float* eWhh1 = (const float*)d_in[7];
    const float* ebih1 = (const float*)d_in[8];
    const float* ebhh1 = (const float*)d_in[9];
    const float* dWih0 = (const float*)d_in[10];
    const float* dWhh0 = (const float*)d_in[11];
    const float* dbih0 = (const float*)d_in[12];
    const float* dbhh0 = (const float*)d_in[13];
    const float* dWih1 = (const float*)d_in[14];
    const float* dWhh1 = (const float*)d_in[15];
    const float* dbih1 = (const float*)d_in[16];
    const float* dbhh1 = (const float*)d_in[17];
    const float* Wmu   = (const float*)d_in[18];
    const float* bmu   = (const float*)d_in[19];
    const float* Wsig  = (const float*)d_in[20];
    const float* bsig  = (const float*)d_in[21];
    float* out = (float*)d_out;

    init_kernel<<<512, 256>>>(out);

    // ---- encoder layer 0 ----
    p_enc0_kernel<<<131072, 256>>>(x, eWih0, ebih0, ebhh0);
    for (int t = 0; t < 256; t++)
        lstm_step_kernel<<<128, 128>>>(eWhh0, t, 0);

    // ---- encoder layer 1 ----
    gemm_bias_kernel<<<dim3(32, 256), 256>>>(eWih1, ebih1, ebhh1);
    for (int t = 0; t < 256; t++)
        lstm_step_kernel<<<128, 128>>>(eWhh1, t, 1);

    // ---- decoder layer 0 ----
    p_dec0_kernel<<<65536, 256>>>(y, dWih0, dbih0, dbhh0);
    for (int t = 0; t < 128; t++)
        lstm_step_kernel<<<128, 128>>>(dWhh0, t, 2);

    // ---- decoder layer 1 ----
    gemm_bias_kernel<<<dim3(32, 128), 256>>>(dWih1, dbih1, dbhh1);
    for (int t = 0; t < 128; t++)
        lstm_step_kernel<<<128, 128>>>(dWhh1, t, 3);

    // ---- head ----
    head_kernel<<<2048, 256>>>(Wmu, bmu, Wsig, bsig, out);
}

// round 2
// speedup vs baseline: 1.0121x; 1.0121x over previous
#include <cuda_runtime.h>
#include <math.h>

typedef unsigned long long u64;

#define BATCH 128
#define HDIM  1024
#define G4    4096

// ---------------- static device scratch (no allocations allowed) ----------------
__device__ float g_P  [(size_t)256 * BATCH * G4];    // 512 MiB: pre-activations for current phase
__device__ float g_hsA[(size_t)256 * BATCH * HDIM];  // 128 MiB: enc L0 hs, reused as dec L0 hs
__device__ float g_hsB[(size_t)128 * BATCH * HDIM];  //  64 MiB: dec L1 hs (head input)
__device__ float g_c0 [BATCH * HDIM];                // layer-0 cell state (enc then dec, in place)
__device__ float g_c1 [BATCH * HDIM];                // layer-1 cell state
__device__ float g_pp [2][BATCH * HDIM];             // h ping-pong for layer-1 recurrences
__device__ float g_zero[BATCH * HDIM];               // all-zero h (never written after init)

// ---------------- f32x2 helpers ----------------
__device__ __forceinline__ u64 pk2(float lo, float hi) {
    u64 r; asm("mov.b64 %0,{%1,%2};" : "=l"(r) : "f"(lo), "f"(hi)); return r;
}
__device__ __forceinline__ void up2(u64 v, float &lo, float &hi) {
    asm("mov.b64 {%0,%1},%2;" : "=f"(lo), "=f"(hi) : "l"(v));
}
__device__ __forceinline__ void ffma2(u64 &d, u64 a, u64 b) {
    asm("fma.rn.f32x2 %0,%1,%2,%0;" : "+l"(d) : "l"(a), "l"(b));
}
__device__ __forceinline__ float sigf(float x) { return 1.0f / (1.0f + expf(-x)); }

// ---------------- init: zero states + the zeros output section ----------------
__global__ void init_kernel(float *out) {
    int i = blockIdx.x * blockDim.x + threadIdx.x;
    if (i < BATCH * HDIM) {
        g_c0[i] = 0.f; g_c1[i] = 0.f;
        g_pp[0][i] = 0.f; g_pp[1][i] = 0.f;
        g_zero[i] = 0.f;
    }
    if (i < 16384) out[i] = 0.f;   // output_collection = zeros
}

// ---------------- P for encoder L0: P[t*B+b][n] = x[b][t][:8] . Wih0[n][:8] + bih+bhh ----------------
__global__ __launch_bounds__(256) void p_enc0_kernel(
    const float* __restrict__ x, const float* __restrict__ W,
    const float* __restrict__ b1, const float* __restrict__ b2)
{
    int idx = blockIdx.x * 256 + threadIdx.x;       // 256*128*1024 float4 units
    int n4 = idx & 1023;
    int b  = (idx >> 10) & 127;
    int t  = idx >> 17;
    const float* xp = x + ((size_t)b * 256 + t) * 8;
    float4 xa = *(const float4*)xp;
    float4 xb = *(const float4*)(xp + 4);
    float res[4];
#pragma unroll
    for (int u = 0; u < 4; u++) {
        int n = n4 * 4 + u;
        const float* wr = W + (size_t)n * 8;
        float4 wa = *(const float4*)wr;
        float4 wb = *(const float4*)(wr + 4);
        res[u] = xa.x*wa.x + xa.y*wa.y + xa.z*wa.z + xa.w*wa.w
               + xb.x*wb.x + xb.y*wb.y + xb.z*wb.z + xb.w*wb.w
               + b1[n] + b2[n];
    }
    *(float4*)(g_P + ((size_t)t * BATCH + b) * G4 + n4 * 4) = make_float4(res[0], res[1], res[2], res[3]);
}

// ---------------- P for decoder L0: P[t*B+b][n] = y[b][t] * Wih0[n] + bih+bhh ----------------
__global__ __launch_bounds__(256) void p_dec0_kernel(
    const float* __restrict__ y, const float* __restrict__ W,
    const float* __restrict__ b1, const float* __restrict__ b2)
{
    int idx = blockIdx.x * 256 + threadIdx.x;       // 128*128*1024 float4 units
    int n4 = idx & 1023;
    int b  = (idx >> 10) & 127;
    int t  = idx >> 17;
    float yv = y[(size_t)b * 129 + t];
    float4 w  = *(const float4*)(W  + n4 * 4);
    float4 v1 = *(const float4*)(b1 + n4 * 4);
    float4 v2 = *(const float4*)(b2 + n4 * 4);
    float4 r;
    r.x = yv * w.x + v1.x + v2.x;
    r.y = yv * w.y + v1.y + v2.y;
    r.z = yv * w.z + v1.z + v2.z;
    r.w = yv * w.w + v1.w + v2.w;
    *(float4*)(g_P + ((size_t)t * BATCH + b) * G4 + n4 * 4) = r;
}

// ---------------- big input GEMM: g_P[m][n] = bias[n] + sum_k g_hsA[m][k] * W[n][k] ----------------
// grid: (32 n-tiles of 128, M/128 m-tiles), 256 threads, 128x128 tile, 8m x 8n per thread (f32x2 on m-pairs)
__global__ __launch_bounds__(256) void gemm_bias_kernel(
    const float* __restrict__ W, const float* __restrict__ b1, const float* __restrict__ b2)
{
    constexpr int KC = 32;
    __shared__ __align__(16) float sA[KC][130];
    __shared__ __align__(16) float sW[KC][132];
    int tid = threadIdx.x;
    int tn = tid & 15, tm = tid >> 4;
    size_t m0 = (size_t)blockIdx.y * 128;
    int n0 = blockIdx.x * 128;

    u64 acc[8][4];
#pragma unroll
    for (int n = 0; n < 8; n++)
#pragma unroll
        for (int p = 0; p < 4; p++) acc[n][p] = 0ull;

    const float* A = g_hsA;
    for (int k0 = 0; k0 < HDIM; k0 += KC) {
#pragma unroll
        for (int bb = 0; bb < 128; bb += 32) {
            int r = bb + (tid >> 3);
            int kk = (tid & 7) * 4;
            float4 v = *(const float4*)(A + (m0 + r) * HDIM + k0 + kk);
            sA[kk+0][r] = v.x; sA[kk+1][r] = v.y; sA[kk+2][r] = v.z; sA[kk+3][r] = v.w;
        }
#pragma unroll
        for (int l = tid; l < 1024; l += 256) {
            int r = l >> 3;
            int kk = (l & 7) * 4;
            float4 v = *(const float4*)(W + (size_t)(n0 + r) * HDIM + k0 + kk);
            sW[kk+0][r] = v.x; sW[kk+1][r] = v.y; sW[kk+2][r] = v.z; sW[kk+3][r] = v.w;
        }
        __syncthreads();
#pragma unroll
        for (int k = 0; k < KC; k++) {
            float2 h0 = *(const float2*)&sA[k][tm*8 + 0];
            float2 h1 = *(const float2*)&sA[k][tm*8 + 2];
            float2 h2 = *(const float2*)&sA[k][tm*8 + 4];
            float2 h3 = *(const float2*)&sA[k][tm*8 + 6];
            u64 a0 = pk2(h0.x, h0.y), a1 = pk2(h1.x, h1.y);
            u64 a2 = pk2(h2.x, h2.y), a3 = pk2(h3.x, h3.y);
            float4 wa = *(const float4*)&sW[k][tn*8];
            float4 wb = *(const float4*)&sW[k][tn*8 + 4];
            u64 w[8] = { pk2(wa.x,wa.x), pk2(wa.y,wa.y), pk2(wa.z,wa.z), pk2(wa.w,wa.w),
                         pk2(wb.x,wb.x), pk2(wb.y,wb.y), pk2(wb.z,wb.z), pk2(wb.w,wb.w) };
#pragma unroll
            for (int n = 0; n < 8; n++) {
                ffma2(acc[n][0], a0, w[n]);
                ffma2(acc[n][1], a1, w[n]);
                ffma2(acc[n][2], a2, w[n]);
                ffma2(acc[n][3], a3, w[n]);
            }
        }
        __syncthreads();
    }

    int nbase = n0 + tn * 8;
    float bias[8];
#pragma unroll
    for (int n = 0; n < 8; n++) bias[n] = b1[nbase + n] + b2[nbase + n];
#pragma unroll
    for (int p = 0; p < 4; p++) {
#pragma unroll
        for (int s = 0; s < 2; s++) {
            float vals[8];
#pragma unroll
            for (int n = 0; n < 8; n++) {
                float lo, hi; up2(acc[n][p], lo, hi);
                vals[n] = (s ? hi : lo) + bias[n];
            }
            size_t m = m0 + tm * 8 + 2 * p + s;
            *(float4*)(g_P + m * G4 + nbase)     = make_float4(vals[0], vals[1], vals[2], vals[3]);
            *(float4*)(g_P + m * G4 + nbase + 4) = make_float4(vals[4], vals[5], vals[6], vals[7]);
        }
    }
}

// ---------------- fused LSTM step: G = P[t] + h_in @ Whh^T ; gates; update h,c ----------------
// grid: 128 blocks (8 j-cols each, all 4 gates), 128 threads.
// thread: jj = tid&7 (one j), bg = tid>>3 (8 batch rows = 4 f32x2 pairs), 4 gates -> 16 acc2.
// phase: 0=enc L0, 1=enc L1, 2=dec L0, 3=dec L1
__global__ __launch_bounds__(128) void lstm_step_kernel(
    const float* __restrict__ Whh, int t, int phase)
{
    constexpr int KC = 32;
    constexpr size_t BH = (size_t)BATCH * HDIM;
    __shared__ __align__(16) float sh[KC][130];   // h^T tile  [k][b]
    __shared__ __align__(16) float sw[KC][36];    // W tile    [k][jj*4+gate]

    const float* P = g_P + (size_t)t * BATCH * G4;
    const float* h_in; float* h_out; float* c;
    if (phase == 0) {
        h_in = (t == 0) ? g_zero : g_hsA + (size_t)(t - 1) * BH;
        h_out = g_hsA + (size_t)t * BH;  c = g_c0;
    } else if (phase == 1) {
        h_in = g_pp[t & 1]; h_out = g_pp[(t + 1) & 1]; c = g_c1;
    } else if (phase == 2) {
        h_in = (t == 0) ? g_hsA + (size_t)255 * BH : g_hsA + (size_t)(t - 1) * BH;
        h_out = g_hsA + (size_t)t * BH;  c = g_c0;
    } else {
        h_in = (t == 0) ? g_pp[0] : g_hsB + (size_t)(t - 1) * BH;
        h_out = g_hsB + (size_t)t * BH;  c = g_c1;
    }

    int tid = threadIdx.x;
    int jj = tid & 7;
    int bg = tid >> 3;            // 0..15  (b base = bg*8)
    int j0 = blockIdx.x * 8;
    int j  = j0 + jj;

    u64 acc[4][4];                 // [gate][b-pair]
#pragma unroll
    for (int gi = 0; gi < 4; gi++)
#pragma unroll
        for (int p = 0; p < 4; p++) acc[gi][p] = 0ull;

    for (int k0 = 0; k0 < HDIM; k0 += KC) {
        // stage h^T tile (coalesced along k)
#pragma unroll
        for (int bb = 0; bb < 128; bb += 16) {
            int b = bb + (tid >> 3);
            int kk = (tid & 7) * 4;
            float4 v = *(const float4*)(h_in + (size_t)b * HDIM + k0 + kk);
            sh[kk+0][b] = v.x; sh[kk+1][b] = v.y; sh[kk+2][b] = v.z; sh[kk+3][b] = v.w;
        }
        // stage W tile: rows n = gate*1024 + j0 + wjj
#pragma unroll
        for (int l = tid; l < 256; l += 128) {
            int cc = l >> 3;
            int kk = (l & 7) * 4;
            int wjj = cc >> 2, gi = cc & 3;
            float4 v = *(const float4*)(Whh + (size_t)(gi * HDIM + j0 + wjj) * HDIM + k0 + kk);
            sw[kk+0][wjj*4+gi] = v.x; sw[kk+1][wjj*4+gi] = v.y;
            sw[kk+2][wjj*4+gi] = v.z; sw[kk+3][wjj*4+gi] = v.w;
        }
        __syncthreads();
#pragma unroll
        for (int k = 0; k < KC; k++) {
            float2 h0 = *(const float2*)&sh[k][bg*8 + 0];
            float2 h1 = *(const float2*)&sh[k][bg*8 + 2];
            float2 h2 = *(const float2*)&sh[k][bg*8 + 4];
            float2 h3 = *(const float2*)&sh[k][bg*8 + 6];
            u64 a0 = pk2(h0.x, h0.y), a1 = pk2(h1.x, h1.y);
            u64 a2 = pk2(h2.x, h2.y), a3 = pk2(h3.x, h3.y);
            float4 w = *(const float4*)&sw[k][jj*4];
            u64 w0 = pk2(w.x, w.x), w1 = pk2(w.y, w.y), w2 = pk2(w.z, w.z), w3 = pk2(w.w, w.w);
            ffma2(acc[0][0], a0, w0); ffma2(acc[0][1], a1, w0); ffma2(acc[0][2], a2, w0); ffma2(acc[0][3], a3, w0);
            ffma2(acc[1][0], a0, w1); ffma2(acc[1][1], a1, w1); ffma2(acc[1][2], a2, w1); ffma2(acc[1][3], a3, w1);
            ffma2(acc[2][0], a0, w2); ffma2(acc[2][1], a1, w2); ffma2(acc[2][2], a2, w2); ffma2(acc[2][3], a3, w2);
            ffma2(acc[3][0], a0, w3); ffma2(acc[3][1], a1, w3); ffma2(acc[3][2], a2, w3); ffma2(acc[3][3], a3, w3);
        }
        __syncthreads();
    }

    // epilogue: gates + state update
#pragma unroll
    for (int p = 0; p < 4; p++) {
        float vi[2], vf[2], vg[2], vo[2];
        up2(acc[0][p], vi[0], vi[1]);
        up2(acc[1][p], vf[0], vf[1]);
        up2(acc[2][p], vg[0], vg[1]);
        up2(acc[3][p], vo[0], vo[1]);
        int b0 = bg * 8 + 2 * p;
#pragma unroll
        for (int s = 0; s < 2; s++) {
            int b = b0 + s;
            const float* Pb = P + (size_t)b * G4;
            float gi = sigf(vi[s] + Pb[j]);
            float gf = sigf(vf[s] + Pb[HDIM + j]);
            float gg = tanhf(vg[s] + Pb[2 * HDIM + j]);
            float go = sigf(vo[s] + Pb[3 * HDIM + j]);
            size_t ci = (size_t)b * HDIM + j;
            float cn = gf * c[ci] + gi * gg;
            c[ci] = cn;
            h_out[ci] = go * tanhf(cn);
        }
    }
}

// ---------------- head: mu / softplus(sigma) from g_hsB ----------------
__global__ __launch_bounds__(256) void head_kernel(
    const float* __restrict__ Wmu, const float* __restrict__ bmu,
    const float* __restrict__ Wsig, const float* __restrict__ bsig,
    float* __restrict__ out)
{
    int gw = (blockIdx.x * 256 + threadIdx.x) >> 5;   // 0..16383, = t*128 + b
    int lane = threadIdx.x & 31;
    if (gw >= 16384) return;
    const float* h = g_hsB + (size_t)gw * HDIM;
    float smu = 0.f, ssg = 0.f;
#pragma unroll 8
    for (int i = lane; i < HDIM; i += 32) {
        float hv = h[i];
        smu += hv * Wmu[i];
        ssg += hv * Wsig[i];
    }
#pragma unroll
    for (int off = 16; off > 0; off >>= 1) {
        smu += __shfl_xor_sync(0xFFFFFFFFu, smu, off);
        ssg += __shfl_xor_sync(0xFFFFFFFFu, ssg, off);
    }
    if (lane == 0) {
        int b = gw & 127;
        int t = gw >> 7;
        float mu = smu + bmu[0];
        float z  = ssg + bsig[0];
        float sp = (z > 0.f) ? (z + log1pf(expf(-z))) : log1pf(expf(z));
        out[16384 + b * 128 + t] = mu;
        out[32768 + b * 128 + t] = sp;
    }
}

// ---------------- launch ----------------
extern "C" void kernel_launch(void* const* d_in, const int* in_sizes, int n_in,
                              void* d_out, int out_size)
{
    (void)in_sizes; (void)n_in; (void)out_size;
    const float* x     = (const float*)d_in[0];
    const float* y     = (const float*)d_in[1];
    const float* eWih0 = (const float*)d_in[2];
    const float* eWhh0 = (const float*)d_in[3];
    const float* ebih0 = (const float*)d_in[4];
    const float* ebhh0 = (const float*)d_in[5];
    const float* eWih1 = (const float*)d_in[6];
    const float* eWhh1 = (const float*)d_in[7];
    const float* ebih1 = (const float*)d_in[8];
    const float* ebhh1 = (const float*)d_in[9];
    const float* dWih0 = (const float*)d_in[10];
    const float* dWhh0 = (const float*)d_in[11];
    const float* dbih0 = (const float*)d_in[12];
    const float* dbhh0 = (const float*)d_in[13];
    const float* dWih1 = (const float*)d_in[14];
    const float* dWhh1 = (const float*)d_in[15];
    const float* dbih1 = (const float*)d_in[16];
    const float* dbhh1 = (const float*)d_in[17];
    const float* Wmu   = (const float*)d_in[18];
    const float* bmu   = (const float*)d_in[19];
    const float* Wsig  = (const float*)d_in[20];
    const float* bsig  = (const float*)d_in[21];
    float* out = (float*)d_out;

    init_kernel<<<512, 256>>>(out);

    // ---- encoder layer 0 ----
    p_enc0_kernel<<<131072, 256>>>(x, eWih0, ebih0, ebhh0);
    for (int t = 0; t < 256; t++)
        lstm_step_kernel<<<128, 128>>>(eWhh0, t, 0);

    // ---- encoder layer 1 ----
    gemm_bias_kernel<<<dim3(32, 256), 256>>>(eWih1, ebih1, ebhh1);
    for (int t = 0; t < 256; t++)
        lstm_step_kernel<<<128, 128>>>(eWhh1, t, 1);

    // ---- decoder layer 0 ----
    p_dec0_kernel<<<65536, 256>>>(y, dWih0, dbih0, dbhh0);
    for (int t = 0; t < 128; t++)
        lstm_step_kernel<<<128, 128>>>(dWhh0, t, 2);

    // ---- decoder layer 1 ----
    gemm_bias_kernel<<<dim3(32, 128), 256>>>(dWih1, dbih1, dbhh1);
    for (int t = 0; t < 128; t++)
        lstm_step_kernel<<<128, 128>>>(dWhh1, t, 3);

    // ---- head ----
    head_kernel<<<2048, 256>>>(Wmu, bmu, Wsig, bsig, out);
}